// round 1
// baseline (speedup 1.0000x reference)
#include <cuda_runtime.h>
#include <cuda_bf16.h>
#include <math.h>

#define NN 50000
#define EE 1600000
#define FIN 512
#define HH 256
#define CC 64

// ---------------- scratch (device globals; no runtime alloc) ----------------
__device__ float g_support1[(size_t)NN * HH];   // x @ W1
__device__ float g_h[(size_t)NN * HH];          // fallback emb storage
__device__ float g_support2[(size_t)NN * CC];   // h @ W2
__device__ int   g_src32[EE];
__device__ int   g_dst32[EE];
__device__ int   g_counts[NN];
__device__ int   g_row_ptr[NN + 1];
__device__ int   g_cursor[NN];
__device__ int   g_csr_src[EE];
__device__ float g_csr_w[EE];
__device__ int   g_is64;

// ---------------- index dtype detection + conversion ----------------
// If the buffer is really int64 (little-endian, values < 2^31), every odd
// int32 word is 0. Sample only within the first EE int32 words (safe for both
// interpretations).
__global__ void detect64_kernel(const int* __restrict__ v) {
    __shared__ int any;
    if (threadIdx.x == 0) any = 0;
    __syncthreads();
    for (int i = threadIdx.x; i < 2048; i += blockDim.x) {
        long long idx = (long long)i * 390;       // < EE/2
        if (v[2 * idx + 1] != 0) any = 1;         // benign race
    }
    __syncthreads();
    if (threadIdx.x == 0) g_is64 = (any ? 0 : 1);
}

__global__ void convert_idx_kernel(const int* __restrict__ src_raw,
                                   const int* __restrict__ dst_raw) {
    int e = blockIdx.x * blockDim.x + threadIdx.x;
    if (e >= EE) return;
    int is64 = g_is64;
    g_src32[e] = is64 ? src_raw[2 * e] : src_raw[e];
    g_dst32[e] = is64 ? dst_raw[2 * e] : dst_raw[e];
}

// ---------------- CSR build ----------------
__global__ void zero_counts_kernel() {
    int i = blockIdx.x * blockDim.x + threadIdx.x;
    if (i < NN) g_counts[i] = 0;
}

__global__ void hist_kernel() {
    int e = blockIdx.x * blockDim.x + threadIdx.x;
    if (e >= EE) return;
    atomicAdd(&g_counts[g_dst32[e]], 1);
}

// Single-block exclusive scan over NN counters (Hillis-Steele per 1024-chunk).
__global__ void scan_kernel() {
    __shared__ int sh[1024];
    __shared__ int carry_sh;
    int t = threadIdx.x;
    if (t == 0) carry_sh = 0;
    __syncthreads();
    for (int base = 0; base < NN; base += 1024) {
        int idx = base + t;
        int v = (idx < NN) ? g_counts[idx] : 0;
        sh[t] = v;
        __syncthreads();
        #pragma unroll
        for (int off = 1; off < 1024; off <<= 1) {
            int x = (t >= off) ? sh[t - off] : 0;
            __syncthreads();
            sh[t] += x;
            __syncthreads();
        }
        int excl = carry_sh + sh[t] - v;
        if (idx < NN) { g_row_ptr[idx] = excl; g_cursor[idx] = excl; }
        __syncthreads();
        if (t == 1023) carry_sh += sh[t];
        __syncthreads();
    }
    if (t == 0) g_row_ptr[NN] = carry_sh;
}

__global__ void scatter_kernel(const float* __restrict__ ew) {
    int e = blockIdx.x * blockDim.x + threadIdx.x;
    if (e >= EE) return;
    int d = g_dst32[e];
    int pos = atomicAdd(&g_cursor[d], 1);
    g_csr_src[pos] = g_src32[e];
    g_csr_w[pos] = ew[e];
}

// ---------------- GEMM1: 128x128x8 SGEMM, 256 thr, 8x8 micro ----------------
__global__ __launch_bounds__(256)
void sgemm_128x128(const float* __restrict__ A, const float* __restrict__ B,
                   float* __restrict__ Cmat, int M, int Nn, int K) {
    __shared__ float As[8][128];
    __shared__ float Bs[8][128];
    const int tid = threadIdx.x;
    const int bn = blockIdx.x * 128;
    const int bm = blockIdx.y * 128;
    const int arow = tid >> 1;
    const int acol = (tid & 1) * 4;
    const int brow = tid >> 5;
    const int bcol = (tid & 31) * 4;
    const int tr = (tid >> 4) * 8;
    const int tc = (tid & 15) * 8;
    float acc[8][8];
    #pragma unroll
    for (int i = 0; i < 8; ++i)
        #pragma unroll
        for (int j = 0; j < 8; ++j) acc[i][j] = 0.f;

    const int grow = bm + arow;
    const float* Aptr = A + (size_t)grow * K + acol;
    const float* Bptr = B + (size_t)brow * Nn + bn + bcol;

    for (int kt = 0; kt < K; kt += 8) {
        float4 a4 = make_float4(0.f, 0.f, 0.f, 0.f);
        if (grow < M) a4 = *reinterpret_cast<const float4*>(Aptr + kt);
        As[acol + 0][arow] = a4.x;
        As[acol + 1][arow] = a4.y;
        As[acol + 2][arow] = a4.z;
        As[acol + 3][arow] = a4.w;
        float4 b4 = *reinterpret_cast<const float4*>(Bptr + (size_t)kt * Nn);
        *reinterpret_cast<float4*>(&Bs[brow][bcol]) = b4;
        __syncthreads();
        #pragma unroll
        for (int k = 0; k < 8; ++k) {
            float ar[8], br[8];
            *(float4*)&ar[0] = *(const float4*)&As[k][tr];
            *(float4*)&ar[4] = *(const float4*)&As[k][tr + 4];
            *(float4*)&br[0] = *(const float4*)&Bs[k][tc];
            *(float4*)&br[4] = *(const float4*)&Bs[k][tc + 4];
            #pragma unroll
            for (int i = 0; i < 8; ++i)
                #pragma unroll
                for (int j = 0; j < 8; ++j)
                    acc[i][j] = fmaf(ar[i], br[j], acc[i][j]);
        }
        __syncthreads();
    }
    #pragma unroll
    for (int i = 0; i < 8; ++i) {
        int r = bm + tr + i;
        if (r < M) {
            float* cp = Cmat + (size_t)r * Nn + bn + tc;
            *(float4*)&cp[0] = *(float4*)&acc[i][0];
            *(float4*)&cp[4] = *(float4*)&acc[i][4];
        }
    }
}

// ---------------- GEMM2: 64x64x16, 256 thr, 4x4 micro ----------------
__global__ __launch_bounds__(256)
void sgemm_64x64(const float* __restrict__ A, const float* __restrict__ B,
                 float* __restrict__ Cmat, int M, int Nn, int K) {
    __shared__ float As[16][64];
    __shared__ float Bs[16][64];
    const int tid = threadIdx.x;
    const int bm = blockIdx.y * 64;
    const int arow = tid >> 2;
    const int acol = (tid & 3) * 4;
    const int brow = tid >> 4;
    const int bcol = (tid & 15) * 4;
    const int tr = (tid >> 4) * 4;
    const int tc = (tid & 15) * 4;
    float acc[4][4];
    #pragma unroll
    for (int i = 0; i < 4; ++i)
        #pragma unroll
        for (int j = 0; j < 4; ++j) acc[i][j] = 0.f;

    const int grow = bm + arow;
    for (int kt = 0; kt < K; kt += 16) {
        float4 a4 = make_float4(0.f, 0.f, 0.f, 0.f);
        if (grow < M)
            a4 = *reinterpret_cast<const float4*>(A + (size_t)grow * K + kt + acol);
        As[acol + 0][arow] = a4.x;
        As[acol + 1][arow] = a4.y;
        As[acol + 2][arow] = a4.z;
        As[acol + 3][arow] = a4.w;
        float4 b4 = *reinterpret_cast<const float4*>(B + (size_t)(kt + brow) * Nn + bcol);
        *reinterpret_cast<float4*>(&Bs[brow][bcol]) = b4;
        __syncthreads();
        #pragma unroll
        for (int k = 0; k < 16; ++k) {
            float ar[4], br[4];
            *(float4*)&ar[0] = *(const float4*)&As[k][tr];
            *(float4*)&br[0] = *(const float4*)&Bs[k][tc];
            #pragma unroll
            for (int i = 0; i < 4; ++i)
                #pragma unroll
                for (int j = 0; j < 4; ++j)
                    acc[i][j] = fmaf(ar[i], br[j], acc[i][j]);
        }
        __syncthreads();
    }
    #pragma unroll
    for (int i = 0; i < 4; ++i) {
        int r = bm + tr + i;
        if (r < M) {
            float* cp = Cmat + (size_t)r * Nn + tc;
            *(float4*)&cp[0] = *(float4*)&acc[i][0];
        }
    }
}

// ---------------- SpMM1: warp per dst row, H=256, fused relu ----------------
__global__ void spmm_relu_256(const float* __restrict__ S, float* __restrict__ out) {
    int warp = (blockIdx.x * blockDim.x + threadIdx.x) >> 5;
    int lane = threadIdx.x & 31;
    if (warp >= NN) return;
    int start = g_row_ptr[warp];
    int end = g_row_ptr[warp + 1];
    float acc[8];
    #pragma unroll
    for (int k = 0; k < 8; ++k) acc[k] = 0.f;
    for (int i = start; i < end; ++i) {
        int src = g_csr_src[i];
        float w = g_csr_w[i];
        const float* row = S + (size_t)src * HH;
        #pragma unroll
        for (int k = 0; k < 8; ++k)
            acc[k] = fmaf(w, __ldg(&row[k * 32 + lane]), acc[k]);
    }
    float* o = out + (size_t)warp * HH;
    #pragma unroll
    for (int k = 0; k < 8; ++k) o[k * 32 + lane] = fmaxf(acc[k], 0.f);
}

// ---------------- SpMM2: warp per dst row, C=64, fused relu+log_softmax -----
__global__ void spmm_relu_lsm_64(const float* __restrict__ S, float* __restrict__ out) {
    int warp = (blockIdx.x * blockDim.x + threadIdx.x) >> 5;
    int lane = threadIdx.x & 31;
    if (warp >= NN) return;
    int start = g_row_ptr[warp];
    int end = g_row_ptr[warp + 1];
    float a0 = 0.f, a1 = 0.f;
    for (int i = start; i < end; ++i) {
        int src = g_csr_src[i];
        float w = g_csr_w[i];
        const float* row = S + (size_t)src * CC;
        a0 = fmaf(w, __ldg(&row[lane]), a0);
        a1 = fmaf(w, __ldg(&row[32 + lane]), a1);
    }
    float v0 = fmaxf(a0, 0.f);
    float v1 = fmaxf(a1, 0.f);
    float m = fmaxf(v0, v1);
    #pragma unroll
    for (int off = 16; off > 0; off >>= 1)
        m = fmaxf(m, __shfl_xor_sync(0xFFFFFFFFu, m, off));
    float s = expf(v0 - m) + expf(v1 - m);
    #pragma unroll
    for (int off = 16; off > 0; off >>= 1)
        s += __shfl_xor_sync(0xFFFFFFFFu, s, off);
    float lse = m + logf(s);
    float* o = out + (size_t)warp * CC;
    o[lane] = v0 - lse;
    o[32 + lane] = v1 - lse;
}

// ---------------- launch ----------------
extern "C" void kernel_launch(void* const* d_in, const int* in_sizes, int n_in,
                              void* d_out, int out_size) {
    const float* x  = (const float*)d_in[0];
    const int*   es = (const int*)d_in[1];   // raw view; dtype resolved on device
    const int*   ed = (const int*)d_in[2];
    const float* ew = (const float*)d_in[3];
    const float* W1 = (const float*)d_in[4];
    const float* W2 = (const float*)d_in[5];
    float* out = (float*)d_out;

    float* support1; float* support2; float* hscratch;
    cudaGetSymbolAddress((void**)&support1, g_support1);
    cudaGetSymbolAddress((void**)&support2, g_support2);
    cudaGetSymbolAddress((void**)&hscratch, g_h);

    float* logp = out;                              // [N, C]
    float* emb;                                     // [N, H]
    if ((size_t)out_size >= (size_t)NN * CC + (size_t)NN * HH)
        emb = out + (size_t)NN * CC;
    else
        emb = hscratch;

    const int TB = 256;
    // 1) index dtype resolution + conversion
    detect64_kernel<<<1, 256>>>(es);
    convert_idx_kernel<<<(EE + TB - 1) / TB, TB>>>(es, ed);
    // 2) CSR build
    zero_counts_kernel<<<(NN + TB - 1) / TB, TB>>>();
    hist_kernel<<<(EE + TB - 1) / TB, TB>>>();
    scan_kernel<<<1, 1024>>>();
    scatter_kernel<<<(EE + TB - 1) / TB, TB>>>(ew);
    // 3) layer 1
    {
        dim3 grid(HH / 128, (NN + 127) / 128);
        sgemm_128x128<<<grid, 256>>>(x, W1, support1, NN, HH, FIN);
    }
    spmm_relu_256<<<(NN * 32 + TB - 1) / TB, TB>>>(support1, emb);
    // 4) layer 2
    {
        dim3 grid(1, (NN + 63) / 64);
        sgemm_64x64<<<grid, 256>>>(emb, W2, support2, NN, CC, HH);
    }
    spmm_relu_lsm_64<<<(NN * 32 + TB - 1) / TB, TB>>>(support2, logp);
}

// round 3
// speedup vs baseline: 1.1928x; 1.1928x over previous
#include <cuda_runtime.h>
#include <cuda_bf16.h>
#include <math.h>

#define NN 50000
#define EE 1600000
#define FIN 512
#define HH 256
#define CC 64
#define NB_SCAN ((NN + 1023) / 1024)

// ---------------- scratch (device globals; no runtime alloc) ----------------
__device__ float g_support1[(size_t)NN * HH];   // x @ W1
__device__ float g_h[(size_t)NN * HH];          // fallback emb storage
__device__ float g_support2[(size_t)NN * CC];   // h @ W2
__device__ int   g_counts[NN];
__device__ int   g_row_ptr[NN + 1];
__device__ int   g_cursor[NN];
__device__ int   g_csr_src[EE];
__device__ float g_csr_w[EE];
__device__ int   g_is64;
__device__ int   g_bsum[64];
__device__ int   g_boff[64];

// ---------------- packed f32x2 helpers (B300 FFMA2 path) ----------------
__device__ __forceinline__ unsigned long long pack2(float x, float y) {
    unsigned long long r;
    asm("mov.b64 %0, {%1, %2};" : "=l"(r) : "f"(x), "f"(y));
    return r;
}
__device__ __forceinline__ void unpack2(unsigned long long v, float& x, float& y) {
    asm("mov.b64 {%0, %1}, %2;" : "=f"(x), "=f"(y) : "l"(v));
}
__device__ __forceinline__ void ffma2(unsigned long long& d, unsigned long long a,
                                      unsigned long long b) {
    asm("fma.rn.f32x2 %0, %1, %2, %0;" : "+l"(d) : "l"(a), "l"(b));
}

// ---------------- index dtype detection ----------------
// int64 little-endian with values < 2^31 => every odd int32 word is 0.
__global__ void detect64_kernel(const int* __restrict__ v) {
    __shared__ int any;
    if (threadIdx.x == 0) any = 0;
    __syncthreads();
    for (int i = threadIdx.x; i < 2048; i += blockDim.x) {
        long long idx = (long long)i * 390;       // < EE/2, safe both ways
        if (v[2 * idx + 1] != 0) any = 1;
    }
    __syncthreads();
    if (threadIdx.x == 0) g_is64 = (any ? 0 : 1);
}

__device__ __forceinline__ int load_idx(const int* __restrict__ p, int e, int is64) {
    return is64 ? p[2 * e] : p[e];
}

// ---------------- CSR build ----------------
__global__ void zero_counts_kernel() {
    int i = blockIdx.x * blockDim.x + threadIdx.x;
    if (i < NN) g_counts[i] = 0;
}

__global__ void hist_kernel(const int* __restrict__ dst_raw) {
    int base = blockIdx.x * blockDim.x * 4 + threadIdx.x;
    int is64 = g_is64;
    #pragma unroll
    for (int k = 0; k < 4; ++k) {
        int e = base + k * blockDim.x;
        if (e < EE) atomicAdd(&g_counts[load_idx(dst_raw, e, is64)], 1);
    }
}

// phase 1: per-block exclusive prescan of counts
__global__ void scan_block_kernel() {
    __shared__ int sh[1024];
    int b = blockIdx.x, t = threadIdx.x;
    int idx = b * 1024 + t;
    int v = (idx < NN) ? g_counts[idx] : 0;
    sh[t] = v;
    __syncthreads();
    #pragma unroll
    for (int off = 1; off < 1024; off <<= 1) {
        int x = (t >= off) ? sh[t - off] : 0;
        __syncthreads();
        sh[t] += x;
        __syncthreads();
    }
    if (idx < NN) g_row_ptr[idx] = sh[t] - v;
    if (t == 1023) g_bsum[b] = sh[1023];
}

// phase 2: scan the block sums (single tiny block)
__global__ void scan_sums_kernel() {
    __shared__ int sh[64];
    int t = threadIdx.x;
    int v = (t < NB_SCAN) ? g_bsum[t] : 0;
    sh[t] = v;
    __syncthreads();
    #pragma unroll
    for (int off = 1; off < 64; off <<= 1) {
        int x = (t >= off) ? sh[t - off] : 0;
        __syncthreads();
        sh[t] += x;
        __syncthreads();
    }
    g_boff[t] = sh[t] - v;
    if (t == 63) g_row_ptr[NN] = sh[63];
}

// phase 3: add block offsets; init cursors
__global__ void scan_add_kernel() {
    int idx = blockIdx.x * 1024 + threadIdx.x;
    if (idx < NN) {
        int r = g_row_ptr[idx] + g_boff[blockIdx.x];
        g_row_ptr[idx] = r;
        g_cursor[idx] = r;
    }
}

__global__ void scatter_kernel(const int* __restrict__ src_raw,
                               const int* __restrict__ dst_raw,
                               const float* __restrict__ ew) {
    int e = blockIdx.x * blockDim.x + threadIdx.x;
    if (e >= EE) return;
    int is64 = g_is64;
    int d = load_idx(dst_raw, e, is64);
    int pos = atomicAdd(&g_cursor[d], 1);
    g_csr_src[pos] = load_idx(src_raw, e, is64);
    g_csr_w[pos] = ew[e];
}

// ---------------- GEMM1: 128x128x8, 256 thr, 8x8 micro, packed f32x2 --------
__global__ __launch_bounds__(256)
void sgemm_128x128(const float* __restrict__ A, const float* __restrict__ B,
                   float* __restrict__ Cmat, int M, int Nn, int K) {
    __shared__ float As[8][128];
    __shared__ float Bs[8][128];
    const int tid = threadIdx.x;
    const int bn = blockIdx.x * 128;
    const int bm = blockIdx.y * 128;
    const int arow = tid >> 1;
    const int acol = (tid & 1) * 4;
    const int brow = tid >> 5;
    const int bcol = (tid & 31) * 4;
    const int tr = (tid >> 4) * 8;
    const int tc = (tid & 15) * 8;          // 8 consecutive N columns = 4 pairs

    unsigned long long acc[8][4];
    #pragma unroll
    for (int i = 0; i < 8; ++i)
        #pragma unroll
        for (int j = 0; j < 4; ++j) acc[i][j] = 0ULL;

    const int grow = bm + arow;
    const float* Aptr = A + (size_t)grow * K + acol;
    const float* Bptr = B + (size_t)brow * Nn + bn + bcol;

    for (int kt = 0; kt < K; kt += 8) {
        float4 a4 = make_float4(0.f, 0.f, 0.f, 0.f);
        if (grow < M) a4 = *reinterpret_cast<const float4*>(Aptr + kt);
        As[acol + 0][arow] = a4.x;
        As[acol + 1][arow] = a4.y;
        As[acol + 2][arow] = a4.z;
        As[acol + 3][arow] = a4.w;
        float4 b4 = *reinterpret_cast<const float4*>(Bptr + (size_t)kt * Nn);
        *reinterpret_cast<float4*>(&Bs[brow][bcol]) = b4;
        __syncthreads();
        #pragma unroll
        for (int k = 0; k < 8; ++k) {
            float ar[8];
            *(float4*)&ar[0] = *(const float4*)&As[k][tr];
            *(float4*)&ar[4] = *(const float4*)&As[k][tr + 4];
            unsigned long long br[4];
            const unsigned long long* bsrow =
                reinterpret_cast<const unsigned long long*>(&Bs[k][0]);
            #pragma unroll
            for (int j = 0; j < 4; ++j) br[j] = bsrow[(tc >> 1) + j];
            #pragma unroll
            for (int i = 0; i < 8; ++i) {
                unsigned long long a2 = pack2(ar[i], ar[i]);
                #pragma unroll
                for (int j = 0; j < 4; ++j) ffma2(acc[i][j], a2, br[j]);
            }
        }
        __syncthreads();
    }
    #pragma unroll
    for (int i = 0; i < 8; ++i) {
        int r = bm + tr + i;
        if (r < M) {
            float outv[8];
            #pragma unroll
            for (int j = 0; j < 4; ++j) unpack2(acc[i][j], outv[2 * j], outv[2 * j + 1]);
            float* cp = Cmat + (size_t)r * Nn + bn + tc;
            *(float4*)&cp[0] = *(float4*)&outv[0];
            *(float4*)&cp[4] = *(float4*)&outv[4];
        }
    }
}

// ---------------- GEMM2: 64x64x16, 256 thr, 4x4 micro, packed f32x2 ---------
__global__ __launch_bounds__(256)
void sgemm_64x64(const float* __restrict__ A, const float* __restrict__ B,
                 float* __restrict__ Cmat, int M, int Nn, int K) {
    __shared__ float As[16][64];
    __shared__ float Bs[16][64];
    const int tid = threadIdx.x;
    const int bm = blockIdx.y * 64;
    const int arow = tid >> 2;
    const int acol = (tid & 3) * 4;
    const int brow = tid >> 4;
    const int bcol = (tid & 15) * 4;
    const int tr = (tid >> 4) * 4;
    const int tc = (tid & 15) * 4;          // 4 consecutive cols = 2 pairs

    unsigned long long acc[4][2];
    #pragma unroll
    for (int i = 0; i < 4; ++i) { acc[i][0] = 0ULL; acc[i][1] = 0ULL; }

    const int grow = bm + arow;
    for (int kt = 0; kt < K; kt += 16) {
        float4 a4 = make_float4(0.f, 0.f, 0.f, 0.f);
        if (grow < M)
            a4 = *reinterpret_cast<const float4*>(A + (size_t)grow * K + kt + acol);
        As[acol + 0][arow] = a4.x;
        As[acol + 1][arow] = a4.y;
        As[acol + 2][arow] = a4.z;
        As[acol + 3][arow] = a4.w;
        float4 b4 = *reinterpret_cast<const float4*>(B + (size_t)(kt + brow) * Nn + bcol);
        *reinterpret_cast<float4*>(&Bs[brow][bcol]) = b4;
        __syncthreads();
        #pragma unroll
        for (int k = 0; k < 16; ++k) {
            float ar[4];
            *(float4*)&ar[0] = *(const float4*)&As[k][tr];
            const unsigned long long* bsrow =
                reinterpret_cast<const unsigned long long*>(&Bs[k][0]);
            unsigned long long br0 = bsrow[(tc >> 1)];
            unsigned long long br1 = bsrow[(tc >> 1) + 1];
            #pragma unroll
            for (int i = 0; i < 4; ++i) {
                unsigned long long a2 = pack2(ar[i], ar[i]);
                ffma2(acc[i][0], a2, br0);
                ffma2(acc[i][1], a2, br1);
            }
        }
        __syncthreads();
    }
    #pragma unroll
    for (int i = 0; i < 4; ++i) {
        int r = bm + tr + i;
        if (r < M) {
            float outv[4];
            unpack2(acc[i][0], outv[0], outv[1]);
            unpack2(acc[i][1], outv[2], outv[3]);
            float* cp = Cmat + (size_t)r * Nn + tc;
            *(float4*)&cp[0] = *(float4*)&outv[0];
        }
    }
}

// ---------------- SpMM1: warp per dst row, H=256, float4, fused relu --------
__global__ void spmm_relu_256(const float* __restrict__ S, float* __restrict__ out) {
    int warp = (blockIdx.x * blockDim.x + threadIdx.x) >> 5;
    int lane = threadIdx.x & 31;
    if (warp >= NN) return;
    int start = g_row_ptr[warp];
    int end = g_row_ptr[warp + 1];
    float4 acc0 = make_float4(0.f, 0.f, 0.f, 0.f);
    float4 acc1 = make_float4(0.f, 0.f, 0.f, 0.f);
    for (int i = start; i < end; ++i) {
        int src = g_csr_src[i];
        float w = g_csr_w[i];
        const float4* row = reinterpret_cast<const float4*>(S + (size_t)src * HH);
        float4 r0 = __ldg(&row[lane]);
        float4 r1 = __ldg(&row[32 + lane]);
        acc0.x = fmaf(w, r0.x, acc0.x); acc0.y = fmaf(w, r0.y, acc0.y);
        acc0.z = fmaf(w, r0.z, acc0.z); acc0.w = fmaf(w, r0.w, acc0.w);
        acc1.x = fmaf(w, r1.x, acc1.x); acc1.y = fmaf(w, r1.y, acc1.y);
        acc1.z = fmaf(w, r1.z, acc1.z); acc1.w = fmaf(w, r1.w, acc1.w);
    }
    float4* o = reinterpret_cast<float4*>(out + (size_t)warp * HH);
    acc0.x = fmaxf(acc0.x, 0.f); acc0.y = fmaxf(acc0.y, 0.f);
    acc0.z = fmaxf(acc0.z, 0.f); acc0.w = fmaxf(acc0.w, 0.f);
    acc1.x = fmaxf(acc1.x, 0.f); acc1.y = fmaxf(acc1.y, 0.f);
    acc1.z = fmaxf(acc1.z, 0.f); acc1.w = fmaxf(acc1.w, 0.f);
    o[lane] = acc0;
    o[32 + lane] = acc1;
}

// ---------------- SpMM2: warp per dst row, C=64, fused relu+log_softmax -----
__global__ void spmm_relu_lsm_64(const float* __restrict__ S, float* __restrict__ out) {
    int warp = (blockIdx.x * blockDim.x + threadIdx.x) >> 5;
    int lane = threadIdx.x & 31;
    if (warp >= NN) return;
    int start = g_row_ptr[warp];
    int end = g_row_ptr[warp + 1];
    float a0 = 0.f, a1 = 0.f;
    for (int i = start; i < end; ++i) {
        int src = g_csr_src[i];
        float w = g_csr_w[i];
        const float2* row = reinterpret_cast<const float2*>(S + (size_t)src * CC);
        float2 r = __ldg(&row[lane]);
        a0 = fmaf(w, r.x, a0);
        a1 = fmaf(w, r.y, a1);
    }
    float v0 = fmaxf(a0, 0.f);
    float v1 = fmaxf(a1, 0.f);
    float m = fmaxf(v0, v1);
    #pragma unroll
    for (int off = 16; off > 0; off >>= 1)
        m = fmaxf(m, __shfl_xor_sync(0xFFFFFFFFu, m, off));
    float s = expf(v0 - m) + expf(v1 - m);
    #pragma unroll
    for (int off = 16; off > 0; off >>= 1)
        s += __shfl_xor_sync(0xFFFFFFFFu, s, off);
    float lse = m + logf(s);
    float* o = out + (size_t)warp * CC;
    o[2 * lane] = v0 - lse;
    o[2 * lane + 1] = v1 - lse;
}

// ---------------- launch ----------------
extern "C" void kernel_launch(void* const* d_in, const int* in_sizes, int n_in,
                              void* d_out, int out_size) {
    const float* x  = (const float*)d_in[0];
    const int*   es = (const int*)d_in[1];   // raw view; dtype resolved on device
    const int*   ed = (const int*)d_in[2];
    const float* ew = (const float*)d_in[3];
    const float* W1 = (const float*)d_in[4];
    const float* W2 = (const float*)d_in[5];
    float* out = (float*)d_out;

    float* support1; float* support2; float* hscratch;
    cudaGetSymbolAddress((void**)&support1, g_support1);
    cudaGetSymbolAddress((void**)&support2, g_support2);
    cudaGetSymbolAddress((void**)&hscratch, g_h);

    float* logp = out;                              // [N, C]
    float* emb;                                     // [N, H]
    if ((size_t)out_size >= (size_t)NN * CC + (size_t)NN * HH)
        emb = out + (size_t)NN * CC;
    else
        emb = hscratch;

    const int TB = 256;
    // 1) index dtype resolution
    detect64_kernel<<<1, 256>>>(es);
    // 2) CSR build (reads raw indices directly; no conversion pass)
    zero_counts_kernel<<<(NN + TB - 1) / TB, TB>>>();
    hist_kernel<<<(EE + TB * 4 - 1) / (TB * 4), TB>>>(ed);
    scan_block_kernel<<<NB_SCAN, 1024>>>();
    scan_sums_kernel<<<1, 64>>>();
    scan_add_kernel<<<NB_SCAN, 1024>>>();
    scatter_kernel<<<(EE + TB - 1) / TB, TB>>>(es, ed, ew);
    // 3) layer 1
    {
        dim3 grid(HH / 128, (NN + 127) / 128);
        sgemm_128x128<<<grid, 256>>>(x, W1, support1, NN, HH, FIN);
    }
    spmm_relu_256<<<(NN * 32 + TB - 1) / TB, TB>>>(support1, emb);
    // 4) layer 2
    {
        dim3 grid(1, (NN + 63) / 64);
        sgemm_64x64<<<grid, 256>>>(emb, W2, support2, NN, CC, HH);
    }
    spmm_relu_lsm_64<<<(NN * 32 + TB - 1) / TB, TB>>>(support2, logp);
}

// round 5
// speedup vs baseline: 1.7514x; 1.4683x over previous
#include <cuda_runtime.h>
#include <cuda_bf16.h>
#include <math.h>
#include <stdint.h>

#define NN 50000
#define EE 1600000
#define FIN 512
#define HH 256
#define CC 64
#define NB_SCAN ((NN + 1023) / 1024)

// ---------------- scratch (device globals; no runtime alloc) ----------------
__device__ float g_support1[(size_t)NN * HH];   // x @ W1
__device__ float g_h[(size_t)NN * HH];          // fallback emb storage
__device__ float g_support2[(size_t)NN * CC];   // h @ W2
__device__ int   g_counts[NN];
__device__ int   g_row_ptr[NN + 1];
__device__ int   g_cursor[NN];
__device__ int   g_csr_src[EE];
__device__ float g_csr_w[EE];
__device__ int   g_is64;
__device__ int   g_bsum[64];
__device__ int   g_boff[64];
__device__ __nv_bfloat16 g_w1t_hi[(size_t)HH * FIN];  // W1^T hi [256][512]
__device__ __nv_bfloat16 g_w1t_lo[(size_t)HH * FIN];  // W1^T lo

// ---------------- packed f32x2 helpers (B300 FFMA2 path) ----------------
__device__ __forceinline__ unsigned long long pack2(float x, float y) {
    unsigned long long r;
    asm("mov.b64 %0, {%1, %2};" : "=l"(r) : "f"(x), "f"(y));
    return r;
}
__device__ __forceinline__ void unpack2(unsigned long long v, float& x, float& y) {
    asm("mov.b64 {%0, %1}, %2;" : "=f"(x), "=f"(y) : "l"(v));
}
__device__ __forceinline__ void ffma2(unsigned long long& d, unsigned long long a,
                                      unsigned long long b) {
    asm("fma.rn.f32x2 %0, %1, %2, %0;" : "+l"(d) : "l"(a), "l"(b));
}

// ---------------- mma.sync helpers (portable HMMA path) ----------------
__device__ __forceinline__ uint32_t smem_u32(const void* p) {
    uint32_t a;
    asm("{ .reg .u64 t; cvta.to.shared.u64 t, %1; cvt.u32.u64 %0, t; }"
        : "=r"(a) : "l"(p));
    return a;
}
__device__ __forceinline__ void ldsm4(uint32_t* r, uint32_t addr) {
    asm volatile("ldmatrix.sync.aligned.m8n8.x4.shared.b16 {%0,%1,%2,%3}, [%4];"
                 : "=r"(r[0]), "=r"(r[1]), "=r"(r[2]), "=r"(r[3]) : "r"(addr));
}
__device__ __forceinline__ void mma16816(float* c, const uint32_t* a, const uint32_t* b) {
    asm volatile(
        "mma.sync.aligned.m16n8k16.row.col.f32.bf16.bf16.f32 "
        "{%0,%1,%2,%3}, {%4,%5,%6,%7}, {%8,%9}, {%0,%1,%2,%3};"
        : "+f"(c[0]), "+f"(c[1]), "+f"(c[2]), "+f"(c[3])
        : "r"(a[0]), "r"(a[1]), "r"(a[2]), "r"(a[3]), "r"(b[0]), "r"(b[1]));
}

// ---------------- index dtype detection ----------------
__global__ void detect64_kernel(const int* __restrict__ v) {
    __shared__ int any;
    if (threadIdx.x == 0) any = 0;
    __syncthreads();
    for (int i = threadIdx.x; i < 2048; i += blockDim.x) {
        long long idx = (long long)i * 390;
        if (v[2 * idx + 1] != 0) any = 1;
    }
    __syncthreads();
    if (threadIdx.x == 0) g_is64 = (any ? 0 : 1);
}

__device__ __forceinline__ int load_idx(const int* __restrict__ p, int e, int is64) {
    return is64 ? p[2 * e] : p[e];
}

// ---------------- CSR build ----------------
__global__ void zero_counts_kernel() {
    int i = blockIdx.x * blockDim.x + threadIdx.x;
    if (i < NN) g_counts[i] = 0;
}

__global__ void hist_kernel(const int* __restrict__ dst_raw) {
    int base = blockIdx.x * blockDim.x * 4 + threadIdx.x;
    int is64 = g_is64;
    #pragma unroll
    for (int k = 0; k < 4; ++k) {
        int e = base + k * blockDim.x;
        if (e < EE) atomicAdd(&g_counts[load_idx(dst_raw, e, is64)], 1);
    }
}

__global__ void scan_block_kernel() {
    __shared__ int sh[1024];
    int b = blockIdx.x, t = threadIdx.x;
    int idx = b * 1024 + t;
    int v = (idx < NN) ? g_counts[idx] : 0;
    sh[t] = v;
    __syncthreads();
    #pragma unroll
    for (int off = 1; off < 1024; off <<= 1) {
        int x = (t >= off) ? sh[t - off] : 0;
        __syncthreads();
        sh[t] += x;
        __syncthreads();
    }
    if (idx < NN) g_row_ptr[idx] = sh[t] - v;
    if (t == 1023) g_bsum[b] = sh[1023];
}

__global__ void scan_sums_kernel() {
    __shared__ int sh[64];
    int t = threadIdx.x;
    int v = (t < NB_SCAN) ? g_bsum[t] : 0;
    sh[t] = v;
    __syncthreads();
    #pragma unroll
    for (int off = 1; off < 64; off <<= 1) {
        int x = (t >= off) ? sh[t - off] : 0;
        __syncthreads();
        sh[t] += x;
        __syncthreads();
    }
    g_boff[t] = sh[t] - v;
    if (t == 63) g_row_ptr[NN] = sh[63];
}

__global__ void scan_add_kernel() {
    int idx = blockIdx.x * 1024 + threadIdx.x;
    if (idx < NN) {
        int r = g_row_ptr[idx] + g_boff[blockIdx.x];
        g_row_ptr[idx] = r;
        g_cursor[idx] = r;
    }
}

__global__ void scatter_kernel(const int* __restrict__ src_raw,
                               const int* __restrict__ dst_raw,
                               const float* __restrict__ ew) {
    int e = blockIdx.x * blockDim.x + threadIdx.x;
    if (e >= EE) return;
    int is64 = g_is64;
    int d = load_idx(dst_raw, e, is64);
    int pos = atomicAdd(&g_cursor[d], 1);
    g_csr_src[pos] = load_idx(src_raw, e, is64);
    g_csr_w[pos] = ew[e];
}

// ---------------- W1 transpose + hi/lo split (once, tiny) ----------------
__global__ void w1_split_kernel(const float* __restrict__ W1) {
    int i = blockIdx.x * blockDim.x + threadIdx.x;   // over FIN*HH
    if (i >= FIN * HH) return;
    int k = i / HH, n = i % HH;
    float v = W1[i];
    __nv_bfloat16 hi = __float2bfloat16(v);
    __nv_bfloat16 lo = __float2bfloat16(v - __bfloat162float(hi));
    g_w1t_hi[(size_t)n * FIN + k] = hi;
    g_w1t_lo[(size_t)n * FIN + k] = lo;
}

// ---------------- GEMM1: HMMA bf16x3 split, CTA 128x128, BK=32 --------------
// acc += Ahi@Bhi + Ahi@Blo + Alo@Bhi ; fp32 accumulators.
#define ASTR 40   // padded row stride (bf16 elems) => 80B, conflict-free ldmatrix

__device__ __forceinline__ uint32_t pack_bf2(float x, float y) {
    __nv_bfloat16 bx = __float2bfloat16(x);
    __nv_bfloat16 by = __float2bfloat16(y);
    return ((uint32_t)__bfloat16_as_ushort(by) << 16) | __bfloat16_as_ushort(bx);
}

__global__ __launch_bounds__(256, 2)
void gemm1_tc(const float* __restrict__ A, float* __restrict__ Cmat) {
    __shared__ __align__(16) unsigned short sAhi[128 * ASTR];
    __shared__ __align__(16) unsigned short sAlo[128 * ASTR];
    __shared__ __align__(16) unsigned short sBhi[128 * ASTR];
    __shared__ __align__(16) unsigned short sBlo[128 * ASTR];

    const int tid = threadIdx.x;
    const int lane = tid & 31;
    const int wid = tid >> 5;
    const int wm = (wid & 3) * 32;        // warp M offset (4 warps down)
    const int wn = (wid >> 2) * 64;       // warp N offset (2 warps across)
    const int bn = blockIdx.x * 128;
    const int bm = blockIdx.y * 128;

    // loader mapping: 2 threads per row; half = 16 elements
    const int lrow = tid >> 1;
    const int lhalf = (tid & 1) * 16;
    const int grow = bm + lrow;

    float acc[2][8][4];
    #pragma unroll
    for (int i = 0; i < 2; ++i)
        #pragma unroll
        for (int j = 0; j < 8; ++j)
            #pragma unroll
            for (int q = 0; q < 4; ++q) acc[i][j][q] = 0.f;

    for (int kt = 0; kt < FIN; kt += 32) {
        // ---- A: fp32 gmem -> hi/lo bf16 smem ----
        {
            uint32_t hi[8], lo[8];
            const float* ap = A + (size_t)grow * FIN + kt + lhalf;
            #pragma unroll
            for (int i = 0; i < 4; ++i) {
                float4 v = make_float4(0.f, 0.f, 0.f, 0.f);
                if (grow < NN) v = *reinterpret_cast<const float4*>(ap + i * 4);
                float hx = __bfloat162float(__float2bfloat16(v.x));
                float hy = __bfloat162float(__float2bfloat16(v.y));
                float hz = __bfloat162float(__float2bfloat16(v.z));
                float hw = __bfloat162float(__float2bfloat16(v.w));
                hi[2 * i]     = pack_bf2(v.x, v.y);
                hi[2 * i + 1] = pack_bf2(v.z, v.w);
                lo[2 * i]     = pack_bf2(v.x - hx, v.y - hy);
                lo[2 * i + 1] = pack_bf2(v.z - hz, v.w - hw);
            }
            uint4* dh = reinterpret_cast<uint4*>(&sAhi[lrow * ASTR + lhalf]);
            uint4* dl = reinterpret_cast<uint4*>(&sAlo[lrow * ASTR + lhalf]);
            dh[0] = make_uint4(hi[0], hi[1], hi[2], hi[3]);
            dh[1] = make_uint4(hi[4], hi[5], hi[6], hi[7]);
            dl[0] = make_uint4(lo[0], lo[1], lo[2], lo[3]);
            dl[1] = make_uint4(lo[4], lo[5], lo[6], lo[7]);
        }
        // ---- B: bf16 gmem (W1^T hi/lo) -> smem ----
        {
            const uint4* bh = reinterpret_cast<const uint4*>(
                g_w1t_hi + (size_t)(bn + lrow) * FIN + kt + lhalf);
            const uint4* bl = reinterpret_cast<const uint4*>(
                g_w1t_lo + (size_t)(bn + lrow) * FIN + kt + lhalf);
            uint4* dh = reinterpret_cast<uint4*>(&sBhi[lrow * ASTR + lhalf]);
            uint4* dl = reinterpret_cast<uint4*>(&sBlo[lrow * ASTR + lhalf]);
            dh[0] = bh[0]; dh[1] = bh[1];
            dl[0] = bl[0]; dl[1] = bl[1];
        }
        __syncthreads();

        #pragma unroll
        for (int k0 = 0; k0 < 32; k0 += 16) {
            // A fragments: 2 m16 tiles, hi + lo
            uint32_t ahi[2][4], alo[2][4];
            const int arow = (lane & 7) + ((lane >> 3) & 1) * 8;
            const int acol = k0 + ((lane >> 4) & 1) * 8;
            #pragma unroll
            for (int mt = 0; mt < 2; ++mt) {
                int r = wm + mt * 16 + arow;
                ldsm4(ahi[mt], smem_u32(&sAhi[r * ASTR + acol]));
                ldsm4(alo[mt], smem_u32(&sAlo[r * ASTR + acol]));
            }
            // B fragments: 4 pairs of n8 tiles
            const int brow = (lane & 7) + ((lane >> 4) & 1) * 8;
            const int bcol = k0 + ((lane >> 3) & 1) * 8;
            #pragma unroll
            for (int ntp = 0; ntp < 4; ++ntp) {
                int nr = wn + ntp * 16 + brow;
                uint32_t bh[4], bl[4];
                ldsm4(bh, smem_u32(&sBhi[nr * ASTR + bcol]));
                ldsm4(bl, smem_u32(&sBlo[nr * ASTR + bcol]));
                #pragma unroll
                for (int mt = 0; mt < 2; ++mt) {
                    mma16816(acc[mt][2 * ntp], ahi[mt], &bh[0]);
                    mma16816(acc[mt][2 * ntp], ahi[mt], &bl[0]);
                    mma16816(acc[mt][2 * ntp], alo[mt], &bh[0]);
                    mma16816(acc[mt][2 * ntp + 1], ahi[mt], &bh[2]);
                    mma16816(acc[mt][2 * ntp + 1], ahi[mt], &bl[2]);
                    mma16816(acc[mt][2 * ntp + 1], alo[mt], &bh[2]);
                }
            }
        }
        __syncthreads();
    }

    // ---- epilogue: direct stores (c0,c1 at row m, c2,c3 at row m+8) ----
    #pragma unroll
    for (int mt = 0; mt < 2; ++mt) {
        int r0 = bm + wm + mt * 16 + (lane >> 2);
        #pragma unroll
        for (int nt = 0; nt < 8; ++nt) {
            int c = bn + wn + nt * 8 + (lane & 3) * 2;
            if (r0 < NN)
                *reinterpret_cast<float2*>(Cmat + (size_t)r0 * HH + c) =
                    make_float2(acc[mt][nt][0], acc[mt][nt][1]);
            if (r0 + 8 < NN)
                *reinterpret_cast<float2*>(Cmat + (size_t)(r0 + 8) * HH + c) =
                    make_float2(acc[mt][nt][2], acc[mt][nt][3]);
        }
    }
}

// ---------------- GEMM2: 64x64x16, 256 thr, 4x4 micro, packed f32x2 ---------
__global__ __launch_bounds__(256)
void sgemm_64x64(const float* __restrict__ A, const float* __restrict__ B,
                 float* __restrict__ Cmat, int M, int Nn, int K) {
    __shared__ float As[16][64];
    __shared__ float Bs[16][64];
    const int tid = threadIdx.x;
    const int bm = blockIdx.y * 64;
    const int arow = tid >> 2;
    const int acol = (tid & 3) * 4;
    const int brow = tid >> 4;
    const int bcol = (tid & 15) * 4;
    const int tr = (tid >> 4) * 4;
    const int tc = (tid & 15) * 4;

    unsigned long long acc[4][2];
    #pragma unroll
    for (int i = 0; i < 4; ++i) { acc[i][0] = 0ULL; acc[i][1] = 0ULL; }

    const int grow = bm + arow;
    for (int kt = 0; kt < K; kt += 16) {
        float4 a4 = make_float4(0.f, 0.f, 0.f, 0.f);
        if (grow < M)
            a4 = *reinterpret_cast<const float4*>(A + (size_t)grow * K + kt + acol);
        As[acol + 0][arow] = a4.x;
        As[acol + 1][arow] = a4.y;
        As[acol + 2][arow] = a4.z;
        As[acol + 3][arow] = a4.w;
        float4 b4 = *reinterpret_cast<const float4*>(B + (size_t)(kt + brow) * Nn + bcol);
        *reinterpret_cast<float4*>(&Bs[brow][bcol]) = b4;
        __syncthreads();
        #pragma unroll
        for (int k = 0; k < 16; ++k) {
            float ar[4];
            *(float4*)&ar[0] = *(const float4*)&As[k][tr];
            const unsigned long long* bsrow =
                reinterpret_cast<const unsigned long long*>(&Bs[k][0]);
            unsigned long long br0 = bsrow[(tc >> 1)];
            unsigned long long br1 = bsrow[(tc >> 1) + 1];
            #pragma unroll
            for (int i = 0; i < 4; ++i) {
                unsigned long long a2 = pack2(ar[i], ar[i]);
                ffma2(acc[i][0], a2, br0);
                ffma2(acc[i][1], a2, br1);
            }
        }
        __syncthreads();
    }
    #pragma unroll
    for (int i = 0; i < 4; ++i) {
        int r = bm + tr + i;
        if (r < M) {
            float outv[4];
            unpack2(acc[i][0], outv[0], outv[1]);
            unpack2(acc[i][1], outv[2], outv[3]);
            float* cp = Cmat + (size_t)r * Nn + tc;
            *(float4*)&cp[0] = *(float4*)&outv[0];
        }
    }
}

// ---------------- SpMM1: warp per dst row, H=256, float4, fused relu --------
__global__ void spmm_relu_256(const float* __restrict__ S, float* __restrict__ out) {
    int warp = (blockIdx.x * blockDim.x + threadIdx.x) >> 5;
    int lane = threadIdx.x & 31;
    if (warp >= NN) return;
    int start = g_row_ptr[warp];
    int end = g_row_ptr[warp + 1];
    float4 acc0 = make_float4(0.f, 0.f, 0.f, 0.f);
    float4 acc1 = make_float4(0.f, 0.f, 0.f, 0.f);
    for (int i = start; i < end; ++i) {
        int src = g_csr_src[i];
        float w = g_csr_w[i];
        const float4* row = reinterpret_cast<const float4*>(S + (size_t)src * HH);
        float4 r0 = __ldg(&row[lane]);
        float4 r1 = __ldg(&row[32 + lane]);
        acc0.x = fmaf(w, r0.x, acc0.x); acc0.y = fmaf(w, r0.y, acc0.y);
        acc0.z = fmaf(w, r0.z, acc0.z); acc0.w = fmaf(w, r0.w, acc0.w);
        acc1.x = fmaf(w, r1.x, acc1.x); acc1.y = fmaf(w, r1.y, acc1.y);
        acc1.z = fmaf(w, r1.z, acc1.z); acc1.w = fmaf(w, r1.w, acc1.w);
    }
    float4* o = reinterpret_cast<float4*>(out + (size_t)warp * HH);
    acc0.x = fmaxf(acc0.x, 0.f); acc0.y = fmaxf(acc0.y, 0.f);
    acc0.z = fmaxf(acc0.z, 0.f); acc0.w = fmaxf(acc0.w, 0.f);
    acc1.x = fmaxf(acc1.x, 0.f); acc1.y = fmaxf(acc1.y, 0.f);
    acc1.z = fmaxf(acc1.z, 0.f); acc1.w = fmaxf(acc1.w, 0.f);
    o[lane] = acc0;
    o[32 + lane] = acc1;
}

// ---------------- SpMM2: warp per dst row, C=64, fused relu+log_softmax -----
__global__ void spmm_relu_lsm_64(const float* __restrict__ S, float* __restrict__ out) {
    int warp = (blockIdx.x * blockDim.x + threadIdx.x) >> 5;
    int lane = threadIdx.x & 31;
    if (warp >= NN) return;
    int start = g_row_ptr[warp];
    int end = g_row_ptr[warp + 1];
    float a0 = 0.f, a1 = 0.f;
    for (int i = start; i < end; ++i) {
        int src = g_csr_src[i];
        float w = g_csr_w[i];
        const float2* row = reinterpret_cast<const float2*>(S + (size_t)src * CC);
        float2 r = __ldg(&row[lane]);
        a0 = fmaf(w, r.x, a0);
        a1 = fmaf(w, r.y, a1);
    }
    float v0 = fmaxf(a0, 0.f);
    float v1 = fmaxf(a1, 0.f);
    float m = fmaxf(v0, v1);
    #pragma unroll
    for (int off = 16; off > 0; off >>= 1)
        m = fmaxf(m, __shfl_xor_sync(0xFFFFFFFFu, m, off));
    float s = expf(v0 - m) + expf(v1 - m);
    #pragma unroll
    for (int off = 16; off > 0; off >>= 1)
        s += __shfl_xor_sync(0xFFFFFFFFu, s, off);
    float lse = m + logf(s);
    float* o = out + (size_t)warp * CC;
    o[2 * lane] = v0 - lse;
    o[2 * lane + 1] = v1 - lse;
}

// ---------------- launch ----------------
extern "C" void kernel_launch(void* const* d_in, const int* in_sizes, int n_in,
                              void* d_out, int out_size) {
    const float* x  = (const float*)d_in[0];
    const int*   es = (const int*)d_in[1];
    const int*   ed = (const int*)d_in[2];
    const float* ew = (const float*)d_in[3];
    const float* W1 = (const float*)d_in[4];
    const float* W2 = (const float*)d_in[5];
    float* out = (float*)d_out;

    float* support1; float* support2; float* hscratch;
    cudaGetSymbolAddress((void**)&support1, g_support1);
    cudaGetSymbolAddress((void**)&support2, g_support2);
    cudaGetSymbolAddress((void**)&hscratch, g_h);

    float* logp = out;
    float* emb;
    if ((size_t)out_size >= (size_t)NN * CC + (size_t)NN * HH)
        emb = out + (size_t)NN * CC;
    else
        emb = hscratch;

    const int TB = 256;
    detect64_kernel<<<1, 256>>>(es);
    zero_counts_kernel<<<(NN + TB - 1) / TB, TB>>>();
    hist_kernel<<<(EE + TB * 4 - 1) / (TB * 4), TB>>>(ed);
    scan_block_kernel<<<NB_SCAN, 1024>>>();
    scan_sums_kernel<<<1, 64>>>();
    scan_add_kernel<<<NB_SCAN, 1024>>>();
    scatter_kernel<<<(EE + TB - 1) / TB, TB>>>(es, ed, ew);
    // layer 1: HMMA split-bf16 GEMM
    w1_split_kernel<<<(FIN * HH + TB - 1) / TB, TB>>>(W1);
    {
        dim3 grid(HH / 128, (NN + 127) / 128);
        gemm1_tc<<<grid, 256>>>(x, support1);
    }
    spmm_relu_256<<<(NN * 32 + TB - 1) / TB, TB>>>(support1, emb);
    // layer 2
    {
        dim3 grid(1, (NN + 63) / 64);
        sgemm_64x64<<<grid, 256>>>(emb, W2, support2, NN, CC, HH);
    }
    spmm_relu_lsm_64<<<(NN * 32 + TB - 1) / TB, TB>>>(support2, logp);
}